// round 8
// baseline (speedup 1.0000x reference)
#include <cuda_runtime.h>
#include <cuda_bf16.h>
#include <mma.h>
#include <cstdint>

using namespace nvcuda;

// Problem constants
constexpr int kB = 2;
constexpr int kT = 2048;
constexpr int kC = 1024;
constexpr int kH = 16;
constexpr int kD = 64;
constexpr int kM = kB * kT;        // 4096
constexpr int kNQKV = 3 * kC;      // 3072
constexpr int kBH = kB * kH;       // 32

// Scratch (static device globals — no allocation allowed)
__device__ float g_qkv[kM * kNQKV];
__device__ float g_q[kBH * kT * kD];
__device__ float g_k[kBH * kT * kD];
__device__ float g_v[kBH * kT * kD];
__device__ float g_att[kM * kC];

// ===========================================================================
// helpers
// ===========================================================================
__device__ __forceinline__ uint32_t smem_u32(const void* p) {
    uint32_t a;
    asm("{ .reg .u64 t; cvta.to.shared.u64 t, %1; cvt.u32.u64 %0, t; }"
        : "=r"(a) : "l"(p));
    return a;
}
__device__ __forceinline__ void cp_async16(void* sdst, const void* gsrc) {
    asm volatile("cp.async.cg.shared.global [%0], [%1], 16;"
                 :: "r"(smem_u32(sdst)), "l"(gsrc) : "memory");
}
__device__ __forceinline__ void cp_commit() {
    asm volatile("cp.async.commit_group;" ::: "memory");
}
__device__ __forceinline__ void cp_wait2() {
    asm volatile("cp.async.wait_group 2;" ::: "memory");
}

// packed f32x2 (FFMA2 path — 2 fp32 MACs per instruction)
union U64f2 { unsigned long long u; float2 f; };
__device__ __forceinline__ void ffma2(unsigned long long& acc,
                                      unsigned long long a, unsigned long long b) {
    asm("fma.rn.f32x2 %0, %1, %2, %0;" : "+l"(acc) : "l"(a), "l"(b));
}
__device__ __forceinline__ float hsum2(unsigned long long p) {
    U64f2 u; u.u = p; return u.f.x + u.f.y;
}
__device__ __forceinline__ unsigned long long bcast2(float x) {
    U64f2 u; u.f.x = x; u.f.y = x; return u.u;
}

// ===========================================================================
// Single-pass TF32 GEMM-NT via WMMA (m16n16k8, fp32 accum), 4-stage cp.async.
// C[m,n] = sum_k A[m,k]*B[n,k], A/B fp32 in GMEM, rounded to tf32 in-fragment
// (RNA, zero-mean error ~2^-11 -> dot rel err ~4e-4 over K=1024).
// Block 128x128, BK=16 fp32/chunk, 8 warps (warp tile 32x64), 1 sync/chunk.
// ===========================================================================
constexpr int kLds = 20;                        // f32 row stride (80B)
constexpr int kStageElems = 2 * 128 * kLds;     // A + B per stage (f32)
constexpr int kGemmSmem = 4 * kStageElems * 4;  // bytes = 81920

__global__ __launch_bounds__(256) void gemm_tf32(
    const float* __restrict__ A, const float* __restrict__ Bm,
    float* __restrict__ Cm, int Nd, int Kd)
{
    extern __shared__ float sm[];

    const int tid = threadIdx.x;
    const int warp = tid >> 5;
    const int wm = warp & 3;
    const int wn = warp >> 2;
    const int row0 = blockIdx.y * 128;
    const int col0 = blockIdx.x * 128;

    const int nchunk = Kd >> 4;         // chunks of 16 f32

    auto issue = [&](int it) {
        const int kc = it << 4;
        float* As = sm + (it & 3) * kStageElems;
        float* Bs = As + 128 * kLds;
#pragma unroll
        for (int s = 0; s < 2; s++) {
            int idx = tid + s * 256;         // 0..511
            int r = idx >> 2;                // row 0..127
            int c4 = (idx & 3) * 4;          // f32 col 0/4/8/12
            cp_async16(&As[r * kLds + c4], A + (size_t)(row0 + r) * Kd + kc + c4);
            cp_async16(&Bs[r * kLds + c4], Bm + (size_t)(col0 + r) * Kd + kc + c4);
        }
    };

    wmma::fragment<wmma::accumulator, 16, 16, 8, float> acc[2][4];
#pragma unroll
    for (int i = 0; i < 2; i++)
#pragma unroll
        for (int j = 0; j < 4; j++)
            wmma::fill_fragment(acc[i][j], 0.f);

    issue(0); cp_commit();
    issue(1); cp_commit();
    issue(2); cp_commit();

    for (int it = 0; it < nchunk; it++) {
        cp_wait2();
        __syncthreads();
        if (it + 3 < nchunk) issue(it + 3);
        cp_commit();

        const float* As = sm + (it & 3) * kStageElems;
        const float* Bs = As + 128 * kLds;
#pragma unroll
        for (int k2 = 0; k2 < 2; k2++) {
            wmma::fragment<wmma::matrix_a, 16, 16, 8,
                           wmma::precision::tf32, wmma::row_major> af[2];
            wmma::fragment<wmma::matrix_b, 16, 16, 8,
                           wmma::precision::tf32, wmma::col_major> bf[4];
#pragma unroll
            for (int i = 0; i < 2; i++) {
                wmma::load_matrix_sync(
                    af[i], &As[(wm * 32 + i * 16) * kLds + k2 * 8], kLds);
#pragma unroll
                for (int t = 0; t < af[i].num_elements; t++)
                    af[i].x[t] = wmma::__float_to_tf32(af[i].x[t]);
            }
#pragma unroll
            for (int j = 0; j < 4; j++) {
                wmma::load_matrix_sync(
                    bf[j], &Bs[(wn * 64 + j * 16) * kLds + k2 * 8], kLds);
#pragma unroll
                for (int t = 0; t < bf[j].num_elements; t++)
                    bf[j].x[t] = wmma::__float_to_tf32(bf[j].x[t]);
            }
#pragma unroll
            for (int i = 0; i < 2; i++)
#pragma unroll
                for (int j = 0; j < 4; j++)
                    wmma::mma_sync(acc[i][j], af[i], bf[j], acc[i][j]);
        }
    }

#pragma unroll
    for (int i = 0; i < 2; i++)
#pragma unroll
        for (int j = 0; j < 4; j++) {
            float* cp = Cm + (size_t)(row0 + wm * 32 + i * 16) * Nd
                           + col0 + wn * 64 + j * 16;
            wmma::store_matrix_sync(cp, acc[i][j], Nd, wmma::mem_row_major);
        }
}

// ===========================================================================
// RoPE + split qkv -> Q/K (roped), V  in [b,h,t,d]
// ===========================================================================
__global__ void rope_split(const float* __restrict__ qkv,
                           const float* __restrict__ cosp,
                           const float* __restrict__ sinp)
{
    int idx = blockIdx.x * blockDim.x + threadIdx.x;
    int dd = idx & 31;
    int rest = idx >> 5;
    int t = rest & (kT - 1);
    rest >>= 11;
    int h = rest & (kH - 1);
    int b = rest >> 4;

    int base = (b * kT + t) * kNQKV + h * kD;
    float c  = cosp[t * 32 + dd];
    float sn = sinp[t * 32 + dd];

    float q1 = qkv[base + dd];
    float q2 = qkv[base + 32 + dd];
    float k1 = qkv[base + kC + dd];
    float k2 = qkv[base + kC + 32 + dd];
    float v1 = qkv[base + 2 * kC + dd];
    float v2 = qkv[base + 2 * kC + 32 + dd];

    int o = ((b * kH + h) * kT + t) * kD + dd;
    g_q[o]      = q1 * c - q2 * sn;
    g_q[o + 32] = q2 * c + q1 * sn;
    g_k[o]      = k1 * c - k2 * sn;
    g_k[o + 32] = k2 * c + k1 * sn;
    g_v[o]      = v1;
    g_v[o + 32] = v2;
}

// ===========================================================================
// Flash attention v5: 64 q/block, 8 q/warp, 64-key tiles. (unchanged core;
// epilogue now writes f32 g_att for the tf32 out-projection)
// ===========================================================================
__global__ __launch_bounds__(256, 2) void flash_attn5()
{
    extern __shared__ float dsm[];
    float (*Ks)[68] = (float (*)[68])dsm;                            // [64][68]
    float (*Vs)[68] = (float (*)[68])(dsm + 64 * 68);                // [64][68]
    float (*Qs)[64] = (float (*)[64])(dsm + 2 * 64 * 68);            // [64][64]
    float (*Ps)[64] = (float (*)[64])(dsm + 2 * 64 * 68 + 64 * 64);  // [64][64]

    const int tid = threadIdx.x, w = tid >> 5, lane = tid & 31;
    const int bh = blockIdx.y;
    const int q0 = blockIdx.x * 64;
    const int qbase = q0 + 8 * w;
    const float L2E = 1.4426950408889634f;

    const float* Qg = g_q + (size_t)bh * kT * kD;
    const float* Kg = g_k + (size_t)bh * kT * kD;
    const float* Vg = g_v + (size_t)bh * kT * kD;

#pragma unroll
    for (int it = 0; it < 4; it++) {
        int idx = tid + it * 256;
        int r = idx >> 4, c4 = (idx & 15) * 4;
        *(float4*)&Qs[r][c4] = *(const float4*)(Qg + (q0 + r) * kD + c4);
    }

    float l[8];
    unsigned long long o[8];
#pragma unroll
    for (int q = 0; q < 8; q++) { l[q] = 0.f; o[q] = 0ull; }

    const int ntiles = blockIdx.x + 1;
    for (int kt = 0; kt < ntiles; kt++) {
        const int kb = kt * 64;
        __syncthreads();
#pragma unroll
        for (int it = 0; it < 4; it++) {
            int idx = tid + it * 256;
            int r = idx >> 4, c4 = (idx & 15) * 4;
            *(float4*)&Ks[r][c4] = *(const float4*)(Kg + (size_t)(kb + r) * kD + c4);
            *(float4*)&Vs[r][c4] = *(const float4*)(Vg + (size_t)(kb + r) * kD + c4);
        }
        __syncthreads();

        // QK^T: lane owns keys kb+lane, kb+lane+32
        unsigned long long a0[8], a1[8];
#pragma unroll
        for (int q = 0; q < 8; q++) { a0[q] = 0ull; a1[q] = 0ull; }
#pragma unroll
        for (int d4 = 0; d4 < 16; d4++) {
            ulonglong2 k0 = *(const ulonglong2*)&Ks[lane][d4 * 4];
            ulonglong2 k1 = *(const ulonglong2*)&Ks[lane + 32][d4 * 4];
#pragma unroll
            for (int q = 0; q < 8; q++) {
                ulonglong2 qp = *(const ulonglong2*)&Qs[8 * w + q][d4 * 4];
                ffma2(a0[q], qp.x, k0.x);
                ffma2(a0[q], qp.y, k0.y);
                ffma2(a1[q], qp.x, k1.x);
                ffma2(a1[q], qp.y, k1.y);
            }
        }

        // max-free softmax; lane-local normalizer
#pragma unroll
        for (int q = 0; q < 8; q++) {
            const int qpos = qbase + q;
            float sa = hsum2(a0[q]) * 0.125f;
            float sb = hsum2(a1[q]) * 0.125f;
            float p0 = (kb + lane      > qpos) ? 0.f : exp2f(sa * L2E);
            float p1 = (kb + lane + 32 > qpos) ? 0.f : exp2f(sb * L2E);
            l[q] += p0 + p1;
            Ps[8 * w + q][lane]      = p0;
            Ps[8 * w + q][lane + 32] = p1;
        }
        __syncwarp();

        // AV: lane owns d-pair (2*lane, 2*lane+1); V read untransposed
#pragma unroll
        for (int k4 = 0; k4 < 16; k4++) {
            float4 pv[8];
#pragma unroll
            for (int q = 0; q < 8; q++)
                pv[q] = *(const float4*)&Ps[8 * w + q][k4 * 4];
#pragma unroll
            for (int j = 0; j < 4; j++) {
                unsigned long long vv =
                    *(const unsigned long long*)&Vs[k4 * 4 + j][2 * lane];
#pragma unroll
                for (int q = 0; q < 8; q++) {
                    float pj = (j == 0) ? pv[q].x : (j == 1) ? pv[q].y
                             : (j == 2) ? pv[q].z : pv[q].w;
                    ffma2(o[q], bcast2(pj), vv);
                }
            }
        }
    }

    // final: reduce normalizers, write f32 output (d-pair per lane)
    const int b = bh >> 4, h = bh & 15;
#pragma unroll
    for (int q = 0; q < 8; q++) {
        float lq = l[q];
#pragma unroll
        for (int off = 16; off; off >>= 1)
            lq += __shfl_xor_sync(0xffffffffu, lq, off);
        float inv = 1.f / lq;
        float* Og = g_att + (size_t)(b * kT + qbase + q) * kC + h * kD + 2 * lane;
        U64f2 u; u.u = o[q];
        *(float2*)Og = make_float2(u.f.x * inv, u.f.y * inv);
    }
}

// ===========================================================================
extern "C" void kernel_launch(void* const* d_in, const int* in_sizes, int n_in,
                              void* d_out, int out_size)
{
    const float* x    = (const float*)d_in[0];
    const float* cosp = (const float*)d_in[1];
    const float* sinp = (const float*)d_in[2];
    // d_in[3] = mask (implicit causal)
    const float* Wqkv = (const float*)d_in[4];
    const float* Wout = (const float*)d_in[5];
    float* out = (float*)d_out;

    float *pqkv, *patt;
    cudaGetSymbolAddress((void**)&pqkv, g_qkv);
    cudaGetSymbolAddress((void**)&patt, g_att);

    const int FLASH_SMEM = (2 * 64 * 68 + 2 * 64 * 64) * 4; // 67584
    cudaFuncSetAttribute(flash_attn5,
                         cudaFuncAttributeMaxDynamicSharedMemorySize, FLASH_SMEM);
    cudaFuncSetAttribute(gemm_tf32,
                         cudaFuncAttributeMaxDynamicSharedMemorySize, kGemmSmem);

    // 1. QKV projection (tf32 tensor cores, reads fp32 inputs directly)
    gemm_tf32<<<dim3(kNQKV / 128, kM / 128), 256, kGemmSmem>>>(
        x, Wqkv, pqkv, kNQKV, kC);

    // 2. RoPE + head split
    rope_split<<<(kBH * kT * 32) / 256, 256>>>(pqkv, cosp, sinp);

    // 3. causal attention -> f32 g_att
    flash_attn5<<<dim3(kT / 64, kBH), 256, FLASH_SMEM>>>();

    // 4. output projection
    gemm_tf32<<<dim3(kC / 128, kM / 128), 256, kGemmSmem>>>(
        patt, Wout, out, kC, kC);
}

// round 11
// speedup vs baseline: 1.2494x; 1.2494x over previous
#include <cuda_runtime.h>
#include <cuda_bf16.h>
#include <mma.h>
#include <cstdint>

using namespace nvcuda;

// Problem constants
constexpr int kB = 2;
constexpr int kT = 2048;
constexpr int kC = 1024;
constexpr int kH = 16;
constexpr int kD = 64;
constexpr int kM = kB * kT;        // 4096
constexpr int kNQKV = 3 * kC;      // 3072
constexpr int kBH = kB * kH;       // 32

// Scratch (static device globals — no allocation allowed)
__device__ float g_qkv[kM * kNQKV];
__device__ __nv_bfloat16 g_qbh[kBH * kT * kD], g_qbl[kBH * kT * kD];
__device__ __nv_bfloat16 g_kbh[kBH * kT * kD], g_kbl[kBH * kT * kD];
__device__ __nv_bfloat16 g_vbh[kBH * kT * kD], g_vbl[kBH * kT * kD];
// split-bf16 GEMM operands
__device__ __nv_bfloat16 g_xh[kM * kC],     g_xl[kM * kC];
__device__ __nv_bfloat16 g_wqh[kNQKV * kC], g_wql[kNQKV * kC];
__device__ __nv_bfloat16 g_ath[kM * kC],    g_atl[kM * kC];
__device__ __nv_bfloat16 g_woh[kC * kC],    g_wol[kC * kC];

// ===========================================================================
// helpers
// ===========================================================================
__device__ __forceinline__ uint32_t smem_u32(const void* p) {
    uint32_t a;
    asm("{ .reg .u64 t; cvta.to.shared.u64 t, %1; cvt.u32.u64 %0, t; }"
        : "=r"(a) : "l"(p));
    return a;
}
__device__ __forceinline__ void cp_async16(void* sdst, const void* gsrc) {
    asm volatile("cp.async.cg.shared.global [%0], [%1], 16;"
                 :: "r"(smem_u32(sdst)), "l"(gsrc) : "memory");
}
__device__ __forceinline__ void cp_commit() {
    asm volatile("cp.async.commit_group;" ::: "memory");
}
__device__ __forceinline__ void cp_wait2() {
    asm volatile("cp.async.wait_group 2;" ::: "memory");
}
__device__ __forceinline__ float fast_exp2(float x) {
    float y;
    asm("ex2.approx.ftz.f32 %0, %1;" : "=f"(y) : "f"(x));
    return y;
}

// ===========================================================================
// Split-bf16 GEMM-NT via WMMA, 4-stage cp.async pipeline (round-5 proven).
// ===========================================================================
constexpr int kLds = 40;
constexpr int kStageElems = 2 * 128 * kLds;
constexpr int kGemmSmem = 4 * kStageElems * 2;

__global__ __launch_bounds__(256) void gemm_wmma_split(
    const __nv_bfloat16* __restrict__ Ah, const __nv_bfloat16* __restrict__ Al,
    const __nv_bfloat16* __restrict__ Bh, const __nv_bfloat16* __restrict__ Bl,
    float* __restrict__ Cm, int Nd, int Kd)
{
    extern __shared__ __nv_bfloat16 sm[];

    const int tid = threadIdx.x;
    const int warp = tid >> 5;
    const int wm = warp & 3;
    const int wn = warp >> 2;
    const int row0 = blockIdx.y * 128;
    const int col0 = blockIdx.x * 128;

    const int nchunk = Kd >> 5;
    const int total = 3 * nchunk;

    auto issue = [&](int it) {
        const int pass = it / nchunk;
        const int kc = (it - pass * nchunk) << 5;
        const __nv_bfloat16* Ap = (pass == 2) ? Al : Ah;
        const __nv_bfloat16* Bp = (pass == 1) ? Bl : Bh;
        __nv_bfloat16* As = sm + (it & 3) * kStageElems;
        __nv_bfloat16* Bs = As + 128 * kLds;
#pragma unroll
        for (int s = 0; s < 2; s++) {
            int idx = tid + s * 256;
            int r = idx >> 2;
            int c8 = (idx & 3) * 8;
            cp_async16(&As[r * kLds + c8], Ap + (size_t)(row0 + r) * Kd + kc + c8);
            cp_async16(&Bs[r * kLds + c8], Bp + (size_t)(col0 + r) * Kd + kc + c8);
        }
    };

    wmma::fragment<wmma::accumulator, 16, 16, 16, float> acc[2][4];
#pragma unroll
    for (int i = 0; i < 2; i++)
#pragma unroll
        for (int j = 0; j < 4; j++)
            wmma::fill_fragment(acc[i][j], 0.f);

    issue(0); cp_commit();
    issue(1); cp_commit();
    issue(2); cp_commit();

    for (int it = 0; it < total; it++) {
        cp_wait2();
        __syncthreads();
        if (it + 3 < total) issue(it + 3);
        cp_commit();

        const __nv_bfloat16* As = sm + (it & 3) * kStageElems;
        const __nv_bfloat16* Bs = As + 128 * kLds;
#pragma unroll
        for (int k2 = 0; k2 < 2; k2++) {
            wmma::fragment<wmma::matrix_a, 16, 16, 16, __nv_bfloat16,
                           wmma::row_major> af[2];
            wmma::fragment<wmma::matrix_b, 16, 16, 16, __nv_bfloat16,
                           wmma::col_major> bf[4];
#pragma unroll
            for (int i = 0; i < 2; i++)
                wmma::load_matrix_sync(
                    af[i], &As[(wm * 32 + i * 16) * kLds + k2 * 16], kLds);
#pragma unroll
            for (int j = 0; j < 4; j++)
                wmma::load_matrix_sync(
                    bf[j], &Bs[(wn * 64 + j * 16) * kLds + k2 * 16], kLds);
#pragma unroll
            for (int i = 0; i < 2; i++)
#pragma unroll
                for (int j = 0; j < 4; j++)
                    wmma::mma_sync(acc[i][j], af[i], bf[j], acc[i][j]);
        }
    }

#pragma unroll
    for (int i = 0; i < 2; i++)
#pragma unroll
        for (int j = 0; j < 4; j++) {
            float* cp = Cm + (size_t)(row0 + wm * 32 + i * 16) * Nd
                           + col0 + wn * 64 + j * 16;
            wmma::store_matrix_sync(cp, acc[i][j], Nd, wmma::mem_row_major);
        }
}

// ===========================================================================
// fp32 -> (hi, lo) bf16 split, 4 elems/thread
// ===========================================================================
__global__ void cvt_hilo4(const float* __restrict__ s,
                          __nv_bfloat16* __restrict__ hi,
                          __nv_bfloat16* __restrict__ lo, int n4)
{
    int i = blockIdx.x * blockDim.x + threadIdx.x;
    if (i < n4) {
        float4 v = ((const float4*)s)[i];
        __nv_bfloat16 h0 = __float2bfloat16(v.x);
        __nv_bfloat16 h1 = __float2bfloat16(v.y);
        __nv_bfloat16 h2 = __float2bfloat16(v.z);
        __nv_bfloat16 h3 = __float2bfloat16(v.w);
        __nv_bfloat162* hp = (__nv_bfloat162*)(hi) + 2 * i;
        __nv_bfloat162* lp = (__nv_bfloat162*)(lo) + 2 * i;
        hp[0] = __nv_bfloat162(h0, h1);
        hp[1] = __nv_bfloat162(h2, h3);
        lp[0] = __nv_bfloat162(__float2bfloat16(v.x - __bfloat162float(h0)),
                               __float2bfloat16(v.y - __bfloat162float(h1)));
        lp[1] = __nv_bfloat162(__float2bfloat16(v.z - __bfloat162float(h2)),
                               __float2bfloat16(v.w - __bfloat162float(h3)));
    }
}

// ===========================================================================
// RoPE + split qkv -> Q/K (roped), V, all hi/lo bf16 in [b,h,t,d]
// ===========================================================================
__device__ __forceinline__ void split_store(__nv_bfloat16* hi, __nv_bfloat16* lo,
                                            int o, float v) {
    __nv_bfloat16 h = __float2bfloat16(v);
    hi[o] = h;
    lo[o] = __float2bfloat16(v - __bfloat162float(h));
}

__global__ void rope_split(const float* __restrict__ qkv,
                           const float* __restrict__ cosp,
                           const float* __restrict__ sinp)
{
    int idx = blockIdx.x * blockDim.x + threadIdx.x;
    int dd = idx & 31;
    int rest = idx >> 5;
    int t = rest & (kT - 1);
    rest >>= 11;
    int h = rest & (kH - 1);
    int b = rest >> 4;

    int base = (b * kT + t) * kNQKV + h * kD;
    float c  = cosp[t * 32 + dd];
    float sn = sinp[t * 32 + dd];

    float q1 = qkv[base + dd];
    float q2 = qkv[base + 32 + dd];
    float k1 = qkv[base + kC + dd];
    float k2 = qkv[base + kC + 32 + dd];
    float v1 = qkv[base + 2 * kC + dd];
    float v2 = qkv[base + 2 * kC + 32 + dd];

    int o = ((b * kH + h) * kT + t) * kD + dd;
    split_store(g_qbh, g_qbl, o,      q1 * c - q2 * sn);
    split_store(g_qbh, g_qbl, o + 32, q2 * c + q1 * sn);
    split_store(g_kbh, g_kbl, o,      k1 * c - k2 * sn);
    split_store(g_kbh, g_kbl, o + 32, k2 * c + k1 * sn);
    split_store(g_vbh, g_vbl, o,      v1);
    split_store(g_vbh, g_vbl, o + 32, v2);
}

// ===========================================================================
// Split-bf16 WMMA flash attention: 64 q/block, 64-key tiles, 8 warps.
// S = Qh Kh + Qh Kl + Ql Kh (fp32 frags) -> smem -> masked exp (max-free) ->
// P split hi/lo -> O += Ph Vh + Ph Vl + Pl Vh. O frags persist across tiles.
// Warp layout: wm = warp&3 (16 rows), wn = warp>>2 (32 cols, 2 frags).
// ===========================================================================
constexpr int kAttnSmem = 8 * 64 * 72 * 2 + 64 * 68 * 4 + 256 * 4; // 92160

__global__ __launch_bounds__(256, 2) void flash_wmma2()
{
    extern __shared__ char smraw[];
    __nv_bfloat16* Qh = (__nv_bfloat16*)smraw;            // each [64][72]
    __nv_bfloat16* Ql  = Qh  + 64 * 72;
    __nv_bfloat16* Kh  = Ql  + 64 * 72;
    __nv_bfloat16* Kl  = Kh  + 64 * 72;
    __nv_bfloat16* Vh  = Kl  + 64 * 72;
    __nv_bfloat16* Vl  = Vh  + 64 * 72;
    __nv_bfloat16* Pbh = Vl  + 64 * 72;
    __nv_bfloat16* Pbl = Pbh + 64 * 72;
    float* Ps = (float*)(Pbl + 64 * 72);                  // [64][68]
    float* lp = Ps + 64 * 68;                             // [4][64]

    const int tid = threadIdx.x, warp = tid >> 5;
    const int wm = warp & 3, wn = warp >> 2;
    const int bh = blockIdx.y;
    const int q0 = blockIdx.x * 64;
    const float L2E = 1.4426950408889634f;

    const size_t hb = (size_t)bh * kT * kD;

    lp[tid] = 0.f;
    // stage Qh/Ql: 2 x 512 x 16B chunks, 4 per thread
#pragma unroll
    for (int s = 0; s < 2; s++) {
        int idx = tid + s * 256;
        int r = idx >> 3, c8 = (idx & 7) * 8;
        *(uint4*)&Qh[r * 72 + c8] = *(const uint4*)(g_qbh + hb + (q0 + r) * kD + c8);
        *(uint4*)&Ql[r * 72 + c8] = *(const uint4*)(g_qbl + hb + (q0 + r) * kD + c8);
    }

    wmma::fragment<wmma::accumulator, 16, 16, 16, float> oacc[2];
#pragma unroll
    for (int j = 0; j < 2; j++) wmma::fill_fragment(oacc[j], 0.f);

    const int ntiles = blockIdx.x + 1;
    for (int kt = 0; kt < ntiles; kt++) {
        const int kb = kt * 64;
        __syncthreads();
#pragma unroll
        for (int s = 0; s < 2; s++) {
            int idx = tid + s * 256;
            int r = idx >> 3, c8 = (idx & 7) * 8;
            size_t g = hb + (size_t)(kb + r) * kD + c8;
            *(uint4*)&Kh[r * 72 + c8] = *(const uint4*)(g_kbh + g);
            *(uint4*)&Kl[r * 72 + c8] = *(const uint4*)(g_kbl + g);
            *(uint4*)&Vh[r * 72 + c8] = *(const uint4*)(g_vbh + g);
            *(uint4*)&Vl[r * 72 + c8] = *(const uint4*)(g_vbl + g);
        }
        __syncthreads();

        // ---- S = Qh Kh + Qh Kl + Ql Kh  (warp tile 16x32)
        wmma::fragment<wmma::accumulator, 16, 16, 16, float> sacc[2];
#pragma unroll
        for (int j = 0; j < 2; j++) wmma::fill_fragment(sacc[j], 0.f);
#pragma unroll
        for (int ks = 0; ks < 4; ks++) {
            wmma::fragment<wmma::matrix_a, 16, 16, 16, __nv_bfloat16,
                           wmma::row_major> ah, al;
            wmma::load_matrix_sync(ah, &Qh[(wm * 16) * 72 + ks * 16], 72);
            wmma::load_matrix_sync(al, &Ql[(wm * 16) * 72 + ks * 16], 72);
#pragma unroll
            for (int j = 0; j < 2; j++) {
                wmma::fragment<wmma::matrix_b, 16, 16, 16, __nv_bfloat16,
                               wmma::col_major> bhf, blf;
                wmma::load_matrix_sync(
                    bhf, &Kh[(wn * 32 + j * 16) * 72 + ks * 16], 72);
                wmma::load_matrix_sync(
                    blf, &Kl[(wn * 32 + j * 16) * 72 + ks * 16], 72);
                wmma::mma_sync(sacc[j], ah, bhf, sacc[j]);
                wmma::mma_sync(sacc[j], ah, blf, sacc[j]);
                wmma::mma_sync(sacc[j], al, bhf, sacc[j]);
            }
        }
#pragma unroll
        for (int j = 0; j < 2; j++)
            wmma::store_matrix_sync(&Ps[(wm * 16) * 68 + wn * 32 + j * 16],
                                    sacc[j], 68, wmma::mem_row_major);
        __syncthreads();

        // ---- masked exp (max-free), row-partial normalizer, P -> hi/lo bf16
        {
            int r = tid >> 2, g = tid & 3;
            int qpos = q0 + r;
            float lsum = 0.f;
#pragma unroll
            for (int i = 0; i < 16; i++) {
                int c = g * 16 + i;
                float s = Ps[r * 68 + c] * 0.125f;
                float p = fast_exp2(s * L2E);
                if (kb + c > qpos) p = 0.f;
                lsum += p;
                __nv_bfloat16 ph = __float2bfloat16(p);
                Pbh[r * 72 + c] = ph;
                Pbl[r * 72 + c] = __float2bfloat16(p - __bfloat162float(ph));
            }
            lp[g * 64 + r] += lsum;
        }
        __syncthreads();

        // ---- O += Ph Vh + Ph Vl + Pl Vh
#pragma unroll
        for (int ks = 0; ks < 4; ks++) {
            wmma::fragment<wmma::matrix_a, 16, 16, 16, __nv_bfloat16,
                           wmma::row_major> ah, al;
            wmma::load_matrix_sync(ah, &Pbh[(wm * 16) * 72 + ks * 16], 72);
            wmma::load_matrix_sync(al, &Pbl[(wm * 16) * 72 + ks * 16], 72);
#pragma unroll
            for (int j = 0; j < 2; j++) {
                wmma::fragment<wmma::matrix_b, 16, 16, 16, __nv_bfloat16,
                               wmma::row_major> bhf, blf;
                wmma::load_matrix_sync(
                    bhf, &Vh[(ks * 16) * 72 + wn * 32 + j * 16], 72);
                wmma::load_matrix_sync(
                    blf, &Vl[(ks * 16) * 72 + wn * 32 + j * 16], 72);
                wmma::mma_sync(oacc[j], ah, bhf, oacc[j]);
                wmma::mma_sync(oacc[j], ah, blf, oacc[j]);
                wmma::mma_sync(oacc[j], al, bhf, oacc[j]);
            }
        }
    }

    // ---- epilogue: O -> smem, normalize rows, write bf16 hi/lo
    __syncthreads();
#pragma unroll
    for (int j = 0; j < 2; j++)
        wmma::store_matrix_sync(&Ps[(wm * 16) * 68 + wn * 32 + j * 16],
                                oacc[j], 68, wmma::mem_row_major);
    __syncthreads();
    {
        int r = tid >> 2, g = tid & 3;
        float lrow = lp[r] + lp[64 + r] + lp[128 + r] + lp[192 + r];
        float inv = 1.f / lrow;
        const int b = bh >> 4, h = bh & 15;
        size_t base = (size_t)(b * kT + q0 + r) * kC + h * kD;
#pragma unroll
        for (int i = 0; i < 16; i++) {
            int c = g * 16 + i;
            float v = Ps[r * 68 + c] * inv;
            __nv_bfloat16 hv = __float2bfloat16(v);
            g_ath[base + c] = hv;
            g_atl[base + c] = __float2bfloat16(v - __bfloat162float(hv));
        }
    }
}

// ===========================================================================
extern "C" void kernel_launch(void* const* d_in, const int* in_sizes, int n_in,
                              void* d_out, int out_size)
{
    const float* x    = (const float*)d_in[0];
    const float* cosp = (const float*)d_in[1];
    const float* sinp = (const float*)d_in[2];
    // d_in[3] = mask (implicit causal)
    const float* Wqkv = (const float*)d_in[4];
    const float* Wout = (const float*)d_in[5];
    float* out = (float*)d_out;

    float* pqkv;
    __nv_bfloat16 *pxh, *pxl, *pwqh, *pwql, *path, *patl, *pwoh, *pwol;
    cudaGetSymbolAddress((void**)&pqkv, g_qkv);
    cudaGetSymbolAddress((void**)&pxh, g_xh);
    cudaGetSymbolAddress((void**)&pxl, g_xl);
    cudaGetSymbolAddress((void**)&pwqh, g_wqh);
    cudaGetSymbolAddress((void**)&pwql, g_wql);
    cudaGetSymbolAddress((void**)&path, g_ath);
    cudaGetSymbolAddress((void**)&patl, g_atl);
    cudaGetSymbolAddress((void**)&pwoh, g_woh);
    cudaGetSymbolAddress((void**)&pwol, g_wol);

    cudaFuncSetAttribute(gemm_wmma_split,
                         cudaFuncAttributeMaxDynamicSharedMemorySize, kGemmSmem);
    cudaFuncSetAttribute(flash_wmma2,
                         cudaFuncAttributeMaxDynamicSharedMemorySize, kAttnSmem);

    // 1. split inputs/weights to bf16 hi/lo
    cvt_hilo4<<<(kM * kC / 4 + 255) / 256, 256>>>(x, pxh, pxl, kM * kC / 4);
    cvt_hilo4<<<(kNQKV * kC / 4 + 255) / 256, 256>>>(Wqkv, pwqh, pwql, kNQKV * kC / 4);
    cvt_hilo4<<<(kC * kC / 4 + 255) / 256, 256>>>(Wout, pwoh, pwol, kC * kC / 4);

    // 2. QKV projection (split-bf16 WMMA)
    gemm_wmma_split<<<dim3(kNQKV / 128, kM / 128), 256, kGemmSmem>>>(
        pxh, pxl, pwqh, pwql, pqkv, kNQKV, kC);

    // 3. RoPE + head split -> hi/lo bf16 Q/K/V
    rope_split<<<(kBH * kT * 32) / 256, 256>>>(pqkv, cosp, sinp);

    // 4. split-bf16 WMMA causal attention (writes bf16 hi/lo directly)
    flash_wmma2<<<dim3(kT / 64, kBH), 256, kAttnSmem>>>();

    // 5. output projection
    gemm_wmma_split<<<dim3(kC / 128, kM / 128), 256, kGemmSmem>>>(
        path, patl, pwoh, pwol, out, kC, kC);
}